// round 5
// baseline (speedup 1.0000x reference)
#include <cuda_runtime.h>
#include <cuda_bf16.h>

#define N 8192
#define TILE 128
#define NTILE (N / TILE)                 // 64
#define NBLK (NTILE * (NTILE + 1) / 2)   // 2080

__device__ double g_partials[NBLK];

__global__ __launch_bounds__(256, 8)
void depth_loss_tiles(const float* __restrict__ p,
                      const float* __restrict__ zs,
                      const float* __restrict__ ns) {
    __shared__ float spi[TILE];
    __shared__ float spj[TILE];

    const int b = blockIdx.x;
    // map linear block id -> lower-triangle tile (I, J), I >= J
    int I = (int)((sqrtf(8.0f * (float)b + 1.0f) - 1.0f) * 0.5f);
    while ((I + 1) * (I + 2) / 2 <= b) I++;
    while (I * (I + 1) / 2 > b) I--;
    const int J = b - I * (I + 1) / 2;

    const int tid = threadIdx.x;
    const float acc = zs[0] * ns[0];     // STEP == 1.0

    if (tid < TILE) spi[tid] = p[I * TILE + tid];
    else            spj[tid - TILE] = p[J * TILE + (tid - TILE)];
    __syncthreads();

    const int r    = tid & (TILE - 1);   // row within tile
    const int half = tid >> 7;           // 0 or 1: which 64-col half
    const int j0   = half * 64;

    const float pi  = spi[r];
    const int   gi  = I * TILE + r;
    const int   gj0 = J * TILE + j0;

    // steps for the first j in this thread's strip; decreases by acc each j.
    // All values are exact multiples of acc in fp32 range -> exact arithmetic.
    float s = (float)(gi - gj0) * acc;

    float sum = 0.0f;
    const float4* pj4 = (const float4*)(spj + j0);

    if (I != J) {
        // fully interior tile: every (i, j) pair is in the lower triangle
        #pragma unroll
        for (int kk = 0; kk < 16; kk++) {
            float4 v = pj4[kk];
            float pj[4] = {v.x, v.y, v.z, v.w};
            #pragma unroll
            for (int e = 0; e < 4; e++) {
                float x = pi - pj[e];
                if (x >= 0.0f) x = fmaf(-0.2f, s, x);
                if (x >= 0.0f) x = fmaxf(fmaf(-0.8f, s, x), 0.0f);
                sum += fabsf(x);
                s -= acc;
            }
        }
    } else {
        // diagonal tile: only pairs with j <= i (i.e. j0+k <= r) contribute
        #pragma unroll
        for (int kk = 0; kk < 16; kk++) {
            float4 v = pj4[kk];
            float pj[4] = {v.x, v.y, v.z, v.w};
            #pragma unroll
            for (int e = 0; e < 4; e++) {
                const int k = kk * 4 + e;
                float x = pi - pj[e];
                if (x >= 0.0f) x = fmaf(-0.2f, s, x);
                if (x >= 0.0f) x = fmaxf(fmaf(-0.8f, s, x), 0.0f);
                if (j0 + k <= r) sum += fabsf(x);
                s -= acc;
            }
        }
    }

    // warp reduce (fp32), then block reduce in fp64
    #pragma unroll
    for (int o = 16; o > 0; o >>= 1)
        sum += __shfl_down_sync(0xffffffffu, sum, o);

    __shared__ double wsum[8];
    if ((tid & 31) == 0) wsum[tid >> 5] = (double)sum;
    __syncthreads();
    if (tid == 0) {
        double t = 0.0;
        #pragma unroll
        for (int w = 0; w < 8; w++) t += wsum[w];
        g_partials[b] = t;
    }
}

__global__ __launch_bounds__(256)
void depth_loss_finalize(float* __restrict__ out) {
    __shared__ double sh[256];
    double t = 0.0;
    for (int i = threadIdx.x; i < NBLK; i += 256) t += g_partials[i];
    sh[threadIdx.x] = t;
    __syncthreads();
    #pragma unroll
    for (int o = 128; o > 0; o >>= 1) {
        if (threadIdx.x < o) sh[threadIdx.x] += sh[threadIdx.x + o];
        __syncthreads();
    }
    if (threadIdx.x == 0)
        out[0] = (float)(sh[0] / ((double)N * (double)N));
}

extern "C" void kernel_launch(void* const* d_in, const int* in_sizes, int n_in,
                              void* d_out, int out_size) {
    const float* p  = (const float*)d_in[0];   // predictions [8192, 1]
    const float* zs = (const float*)d_in[1];   // z_spacing scalar
    const float* ns = (const float*)d_in[2];   // nth_slice scalar
    float* out = (float*)d_out;

    depth_loss_tiles<<<NBLK, 256>>>(p, zs, ns);
    depth_loss_finalize<<<1, 256>>>(out);
}

// round 6
// speedup vs baseline: 1.0017x; 1.0017x over previous
#include <cuda_runtime.h>
#include <cuda_bf16.h>

#define N 8192
#define TILE 128
#define NTILE (N / TILE)                 // 64
#define NBLK (NTILE * (NTILE + 1) / 2)   // 2080

__device__ double g_partials[NBLK];
__device__ unsigned int g_count = 0;

__global__ __launch_bounds__(256, 8)
void depth_loss_fused(const float* __restrict__ p,
                      const float* __restrict__ zs,
                      const float* __restrict__ ns,
                      float* __restrict__ out) {
    __shared__ float spi[TILE];
    __shared__ float spj[TILE];
    __shared__ float sbj[TILE];   // p[j] - 0.2*acc*j
    __shared__ float sdj[TILE];   // p[j] - acc*j
    __shared__ int   s_last;

    const int b = blockIdx.x;
    // linear block id -> lower-triangle tile (I, J), I >= J
    int I = (int)((sqrtf(8.0f * (float)b + 1.0f) - 1.0f) * 0.5f);
    while ((I + 1) * (I + 2) / 2 <= b) I++;
    while (I * (I + 1) / 2 > b) I--;
    const int J = b - I * (I + 1) / 2;

    const int tid = threadIdx.x;
    const float acc = zs[0] * ns[0];     // STEP == 1.0
    const float c1  = 0.2f * acc;

    if (tid < TILE) {
        spi[tid] = p[I * TILE + tid];
    } else {
        const int jj = tid - TILE;
        const int gj = J * TILE + jj;
        const float v = p[gj];
        spj[jj] = v;
        sbj[jj] = v - c1  * (float)gj;
        sdj[jj] = v - acc * (float)gj;
    }
    __syncthreads();

    const int r    = tid & (TILE - 1);   // row within tile
    const int half = tid >> 7;           // which 64-col half
    const int j0   = half * 64;

    const float pi = spi[r];
    const int   gi = I * TILE + r;
    const float ai = pi - c1  * (float)gi;   // hoisted: x - 0.2s == ai - bj
    const float ci = pi - acc * (float)gi;   // hoisted: x -    s == ci - dj

    float sum = 0.0f;
    const float4* pj4 = (const float4*)(spj + j0);
    const float4* bj4 = (const float4*)(sbj + j0);
    const float4* dj4 = (const float4*)(sdj + j0);

    if (I != J) {
        // interior tile: every pair is strictly lower-triangle (s > 0)
        #pragma unroll
        for (int kk = 0; kk < 16; kk++) {
            float4 vp = pj4[kk];
            float4 vb = bj4[kk];
            float4 vd = dj4[kk];
            float P[4] = {vp.x, vp.y, vp.z, vp.w};
            float B[4] = {vb.x, vb.y, vb.z, vb.w};
            float D[4] = {vd.x, vd.y, vd.z, vd.w};
            #pragma unroll
            for (int e = 0; e < 4; e++) {
                float y = ai - B[e];              // x - 0.2s
                float z = ci - D[e];              // x - s
                float w = P[e] - pi;              // -x
                float A = fmaxf(-y, fmaxf(z, 0.0f));
                sum += (w > 0.0f) ? w : A;        // x<0 ? |x| : piecewise
            }
        }
    } else {
        // diagonal tile: only j <= i contributes
        #pragma unroll
        for (int kk = 0; kk < 16; kk++) {
            float4 vp = pj4[kk];
            float4 vb = bj4[kk];
            float4 vd = dj4[kk];
            float P[4] = {vp.x, vp.y, vp.z, vp.w};
            float B[4] = {vb.x, vb.y, vb.z, vb.w};
            float D[4] = {vd.x, vd.y, vd.z, vd.w};
            #pragma unroll
            for (int e = 0; e < 4; e++) {
                const int k = kk * 4 + e;
                float y = ai - B[e];
                float z = ci - D[e];
                float w = P[e] - pi;
                float A = fmaxf(-y, fmaxf(z, 0.0f));
                float f = (w > 0.0f) ? w : A;
                sum += (j0 + k <= r) ? f : 0.0f;
            }
        }
    }

    // warp reduce fp32
    #pragma unroll
    for (int o = 16; o > 0; o >>= 1)
        sum += __shfl_down_sync(0xffffffffu, sum, o);

    __shared__ float wsum[8];
    if ((tid & 31) == 0) wsum[tid >> 5] = sum;
    __syncthreads();
    if (tid == 0) {
        double t = 0.0;
        #pragma unroll
        for (int w = 0; w < 8; w++) t += (double)wsum[w];
        g_partials[b] = t;
        __threadfence();
        unsigned c = atomicAdd(&g_count, 1u);
        s_last = (c == (unsigned)(NBLK - 1)) ? 1 : 0;
    }
    __syncthreads();

    if (s_last) {
        // last block: deterministic final reduction (L2-hot partials)
        double t = 0.0;
        for (int i = tid; i < NBLK; i += 256)
            t += __ldcg(&g_partials[i]);
        #pragma unroll
        for (int o = 16; o > 0; o >>= 1)
            t += __shfl_down_sync(0xffffffffu, t, o);
        __shared__ double dsum[8];
        if ((tid & 31) == 0) dsum[tid >> 5] = t;
        __syncthreads();
        if (tid == 0) {
            double tot = 0.0;
            #pragma unroll
            for (int w = 0; w < 8; w++) tot += dsum[w];
            out[0] = (float)(tot / ((double)N * (double)N));
            g_count = 0;   // reset for next graph replay
        }
    }
}

extern "C" void kernel_launch(void* const* d_in, const int* in_sizes, int n_in,
                              void* d_out, int out_size) {
    const float* p  = (const float*)d_in[0];   // predictions [8192, 1]
    const float* zs = (const float*)d_in[1];   // z_spacing scalar
    const float* ns = (const float*)d_in[2];   // nth_slice scalar
    float* out = (float*)d_out;

    depth_loss_fused<<<NBLK, 256>>>(p, zs, ns, out);
}